// round 3
// baseline (speedup 1.0000x reference)
#include <cuda_runtime.h>
#include <math.h>

#define BB 2
#define SS 2048
#define EE 1024
#define HH 16
#define DD 64
#define MROWS (BB*SS)            // 4096
#define QK (SS*SS)               // 4194304 per (b,h) score matrix

// Scratch (allocation-free rule: __device__ globals)
__device__ float g_q [MROWS*EE];
__device__ float g_k [MROWS*EE];
__device__ float g_v [MROWS*EE];
__device__ float g_ao[MROWS*EE];
__device__ float g_p [134217728];   // [B,H,S,S] scores/probs, 536 MB

// ---------------------------------------------------------------------------
// Generic tiled fp32 GEMM:
//   C[m,n] = alpha * sum_k A[m,k] * B'(k,n)  (+ bias[n])
//   BNT=true : B' = B^T, B stored [N,K] row-major (K contiguous)  -> x @ W.T
//   BNT=false: B' = B,   B stored [K,N] row-major (N contiguous)  -> P @ V
// Batched over blockIdx.z with (z/HH, z%HH) offsets so per-(batch,head)
// strided views of Q/K/V work without extra copies.
// ---------------------------------------------------------------------------
template<int BM,int BN,int BK,int TM,int TN,bool BNT>
__global__ void __launch_bounds__(256)
gemm_k(int M,int N,int K,
       const float* __restrict__ A, int lda, long sAb, long sAh,
       const float* __restrict__ Bp, int ldb, long sBb, long sBh,
       float* __restrict__ C, int ldc, long sCb, long sCh,
       const float* __restrict__ bias, float alpha)
{
    constexpr int TX = BN/TN, TY = BM/TM, NTH = TX*TY;
    __shared__ float As[BK][BM+4];
    __shared__ float Bs[BK][BN+4];

    const int z  = blockIdx.z;
    const int zb = z / HH, zh = z % HH;
    A  += (long)zb*sAb + (long)zh*sAh;
    Bp += (long)zb*sBb + (long)zh*sBh;
    C  += (long)zb*sCb + (long)zh*sCh;

    const int m0 = blockIdx.y*BM, n0 = blockIdx.x*BN;
    const int tid = threadIdx.x;
    const int tx = tid % TX, ty = tid / TX;

    float acc[TM][TN];
#pragma unroll
    for (int i=0;i<TM;i++)
#pragma unroll
        for (int j=0;j<TN;j++) acc[i][j] = 0.f;

    for (int k0=0; k0<K; k0+=BK) {
        // Load A tile (BM x BK), K contiguous -> float4 along k
        for (int i = tid*4; i < BM*BK; i += NTH*4) {
            int r = i/BK, kk = i%BK;
            float4 t = *(const float4*)(A + (long)(m0+r)*lda + (k0+kk));
            As[kk+0][r]=t.x; As[kk+1][r]=t.y; As[kk+2][r]=t.z; As[kk+3][r]=t.w;
        }
        if (BNT) {
            for (int i = tid*4; i < BN*BK; i += NTH*4) {
                int r = i/BK, kk = i%BK;
                float4 t = *(const float4*)(Bp + (long)(n0+r)*ldb + (k0+kk));
                Bs[kk+0][r]=t.x; Bs[kk+1][r]=t.y; Bs[kk+2][r]=t.z; Bs[kk+3][r]=t.w;
            }
        } else {
            for (int i = tid*4; i < BK*BN; i += NTH*4) {
                int kk = i/BN, c = i%BN;
                float4 t = *(const float4*)(Bp + (long)(k0+kk)*ldb + (n0+c));
                Bs[kk][c+0]=t.x; Bs[kk][c+1]=t.y; Bs[kk][c+2]=t.z; Bs[kk][c+3]=t.w;
            }
        }
        __syncthreads();

#pragma unroll
        for (int kk=0; kk<BK; kk++) {
            float ra[TM], rb[TN];
#pragma unroll
            for (int i=0;i<TM;i++) ra[i] = As[kk][ty*TM+i];
#pragma unroll
            for (int j=0;j<TN;j++) rb[j] = Bs[kk][tx*TN+j];
#pragma unroll
            for (int i=0;i<TM;i++)
#pragma unroll
                for (int j=0;j<TN;j++)
                    acc[i][j] = fmaf(ra[i], rb[j], acc[i][j]);
        }
        __syncthreads();
    }

#pragma unroll
    for (int i=0;i<TM;i++) {
        const int row = m0 + ty*TM + i;
#pragma unroll
        for (int j=0;j<TN;j++) {
            const int col = n0 + tx*TN + j;
            float vv = acc[i][j]*alpha;
            if (bias) vv += bias[col];
            C[(long)row*ldc + col] = vv;
        }
    }
}

// ---------------------------------------------------------------------------
// Softmax over the HEADS axis of P[B,H,S,S]: for each (b,q,k), normalize
// the 16 values across h (faithful to the reference's axis=1 quirk).
// ---------------------------------------------------------------------------
__global__ void softmax_heads_k(float* __restrict__ P)
{
    const long total = (long)BB*SS*SS;
    long idx = (long)blockIdx.x*blockDim.x + threadIdx.x;
    if (idx >= total) return;
    long b  = idx / (long)QK;
    long qk = idx - b*(long)QK;
    float* p = P + b*(long)HH*QK + qk;

    float v[HH];
    float m = -1e30f;
#pragma unroll
    for (int h=0; h<HH; h++) { v[h] = p[(long)h*QK]; m = fmaxf(m, v[h]); }
    float s = 0.f;
#pragma unroll
    for (int h=0; h<HH; h++) { v[h] = __expf(v[h]-m); s += v[h]; }
    const float inv = 1.f/s;
#pragma unroll
    for (int h=0; h<HH; h++) p[(long)h*QK] = v[h]*inv;
}

// ---------------------------------------------------------------------------
extern "C" void kernel_launch(void* const* d_in, const int* in_sizes, int n_in,
                              void* d_out, int out_size)
{
    const float* x  = (const float*)d_in[0];
    const float* Wq = (const float*)d_in[1];
    const float* bq = (const float*)d_in[2];
    const float* Wk = (const float*)d_in[3];
    const float* bk = (const float*)d_in[4];
    const float* Wv = (const float*)d_in[5];
    const float* bv = (const float*)d_in[6];
    const float* Wo = (const float*)d_in[7];
    const float* bo = (const float*)d_in[8];
    float* out = (float*)d_out;

    float *q,*k,*v,*ao,*p;
    cudaGetSymbolAddress((void**)&q,  g_q);
    cudaGetSymbolAddress((void**)&k,  g_k);
    cudaGetSymbolAddress((void**)&v,  g_v);
    cudaGetSymbolAddress((void**)&ao, g_ao);
    cudaGetSymbolAddress((void**)&p,  g_p);

    dim3 blk(256);

    // Q/K/V projections: [4096,1024] = x[4096,1024] @ W^T + b
    {
        dim3 g(EE/128, MROWS/128, 1);
        gemm_k<128,128,16,8,8,true><<<g,blk>>>(MROWS,EE,EE,
            x,EE,0,0,  Wq,EE,0,0,  q,EE,0,0,  bq, 1.f);
        gemm_k<128,128,16,8,8,true><<<g,blk>>>(MROWS,EE,EE,
            x,EE,0,0,  Wk,EE,0,0,  k,EE,0,0,  bk, 1.f);
        gemm_k<128,128,16,8,8,true><<<g,blk>>>(MROWS,EE,EE,
            x,EE,0,0,  Wv,EE,0,0,  v,EE,0,0,  bv, 1.f);
    }

    // Scores: per (b,h): S[q,kk] = (1/8) * Q_bh[q,:] . K_bh[kk,:]   (D=64)
    {
        dim3 g(SS/128, SS/128, BB*HH);
        gemm_k<128,128,16,8,8,true><<<g,blk>>>(SS,SS,DD,
            q,EE,(long)SS*EE,(long)DD,
            k,EE,(long)SS*EE,(long)DD,
            p,SS,(long)HH*QK,(long)QK,
            nullptr, 0.125f);
    }

    // Softmax across heads (in place)
    {
        long total = (long)BB*SS*SS;
        int nb = (int)((total + 255)/256);
        softmax_heads_k<<<nb,256>>>(p);
    }

    // attn @ V: per (b,h): AO[q, h*64+d] = sum_k P[q,k] * V[b,k,h*64+d]
    {
        dim3 g(DD/64, SS/128, BB*HH);
        gemm_k<128,64,16,8,4,false><<<g,blk>>>(SS,DD,SS,
            p,SS,(long)HH*QK,(long)QK,
            v,EE,(long)SS*EE,(long)DD,
            ao,EE,(long)SS*EE,(long)DD,
            nullptr, 1.f);
    }

    // Output projection into d_out
    {
        dim3 g(EE/128, MROWS/128, 1);
        gemm_k<128,128,16,8,8,true><<<g,blk>>>(MROWS,EE,EE,
            ao,EE,0,0,  Wo,EE,0,0,  out,EE,0,0,  bo, 1.f);
    }
}

// round 4
// speedup vs baseline: 2.3163x; 2.3163x over previous
#include <cuda_runtime.h>
#include <math.h>

#define BB 2
#define SS 2048
#define EE 1024
#define HH 16
#define DD 64
#define MROWS (BB*SS)            // 4096
#define QK (SS*SS)               // 4194304 per (b,h)

// Scratch (allocation-free rule: __device__ globals)
__device__ float g_q [MROWS*EE];
__device__ float g_k [MROWS*EE];
__device__ float g_v [MROWS*EE];
__device__ float g_ao[MROWS*EE];
__device__ float g_p [134217728];   // [B,H,S,S] probs, 536 MB

// ---------------------------------------------------------------------------
// tf32 helpers
// ---------------------------------------------------------------------------
__device__ __forceinline__ unsigned f2t(float f){
    unsigned r; asm("cvt.rna.tf32.f32 %0, %1;" : "=r"(r) : "f"(f)); return r;
}
__device__ __forceinline__ void mma8(float* c, const unsigned* a, const unsigned* b){
    asm volatile("mma.sync.aligned.m16n8k8.row.col.f32.tf32.tf32.f32 "
        "{%0,%1,%2,%3},{%4,%5,%6,%7},{%8,%9},{%0,%1,%2,%3};"
        : "+f"(c[0]),"+f"(c[1]),"+f"(c[2]),"+f"(c[3])
        : "r"(a[0]),"r"(a[1]),"r"(a[2]),"r"(a[3]),"r"(b[0]),"r"(b[1]));
}

// ---------------------------------------------------------------------------
// Projection GEMM: C[4096,1024] = A[4096,1024] @ W[1024,1024]^T (+ bias)
// BM=128 BN=128 BK=16, 8 warps (4m x 2n), warp tile 32x64. Double-buffered.
// ---------------------------------------------------------------------------
__global__ void __launch_bounds__(256,1)
proj_tf32(const float* __restrict__ A, const float* __restrict__ W,
          const float* __restrict__ bias, float* __restrict__ C)
{
    constexpr int BK=16, LD=BK+4;   // pad -> conflict-free frag reads
    __shared__ unsigned As[2][128*LD], Bs[2][128*LD];
    const int tid=threadIdx.x, lane=tid&31, wid=tid>>5;
    const int g=lane>>2, t=lane&3;
    const int wm=wid>>1, wn=wid&1;
    const int m0=blockIdx.y*128, n0=blockIdx.x*128;
    const int lr=tid>>2, lc=(tid&3)<<2;

    float4 pa[2], pb[2];
    auto ldg=[&](int kt){
#pragma unroll
        for(int j=0;j<2;j++){
            pa[j]=*(const float4*)(A+(long)(m0+lr+j*64)*EE+kt*BK+lc);
            pb[j]=*(const float4*)(W+(long)(n0+lr+j*64)*EE+kt*BK+lc);
        }
    };
    auto sts=[&](int buf){
#pragma unroll
        for(int j=0;j<2;j++){
            int r=lr+j*64;
            As[buf][r*LD+lc  ]=f2t(pa[j].x); As[buf][r*LD+lc+1]=f2t(pa[j].y);
            As[buf][r*LD+lc+2]=f2t(pa[j].z); As[buf][r*LD+lc+3]=f2t(pa[j].w);
            Bs[buf][r*LD+lc  ]=f2t(pb[j].x); Bs[buf][r*LD+lc+1]=f2t(pb[j].y);
            Bs[buf][r*LD+lc+2]=f2t(pb[j].z); Bs[buf][r*LD+lc+3]=f2t(pb[j].w);
        }
    };

    float acc[2][8][4];
#pragma unroll
    for(int i=0;i<2;i++)
#pragma unroll
        for(int j=0;j<8;j++)
#pragma unroll
            for(int k=0;k<4;k++) acc[i][j][k]=0.f;

    const int NT=EE/BK;   // 64
    ldg(0); sts(0); __syncthreads();
    for(int kt=0;kt<NT;kt++){
        const int buf=kt&1;
        if(kt+1<NT) ldg(kt+1);
#pragma unroll
        for(int kk=0;kk<2;kk++){
            unsigned af[2][4], bf[8][2];
#pragma unroll
            for(int mi=0;mi<2;mi++){
                const int rb=wm*32+mi*16;
                af[mi][0]=As[buf][(rb+g  )*LD+kk*8+t  ];
                af[mi][1]=As[buf][(rb+g+8)*LD+kk*8+t  ];
                af[mi][2]=As[buf][(rb+g  )*LD+kk*8+t+4];
                af[mi][3]=As[buf][(rb+g+8)*LD+kk*8+t+4];
            }
#pragma unroll
            for(int nj=0;nj<8;nj++){
                const int nb=wn*64+nj*8+g;
                bf[nj][0]=Bs[buf][nb*LD+kk*8+t  ];
                bf[nj][1]=Bs[buf][nb*LD+kk*8+t+4];
            }
#pragma unroll
            for(int mi=0;mi<2;mi++)
#pragma unroll
                for(int nj=0;nj<8;nj++)
                    mma8(acc[mi][nj],af[mi],bf[nj]);
        }
        if(kt+1<NT) sts((kt+1)&1);
        __syncthreads();
    }
#pragma unroll
    for(int mi=0;mi<2;mi++){
        const int r0=m0+wm*32+mi*16+g;
#pragma unroll
        for(int nj=0;nj<8;nj++){
            const int col=n0+wn*64+nj*8+2*t;
            float b0=bias[col], b1=bias[col+1];
            float2 v0={acc[mi][nj][0]+b0, acc[mi][nj][1]+b1};
            float2 v1={acc[mi][nj][2]+b0, acc[mi][nj][3]+b1};
            *(float2*)(C+(long)r0*EE+col)=v0;
            *(float2*)(C+(long)(r0+8)*EE+col)=v1;
        }
    }
}

// ---------------------------------------------------------------------------
// Fused scores + heads-softmax.
// CTA = (b, q-tile 64, k-tile 32). For all 16 heads: S_h = Q_h K_h^T / 8.
// Each thread holds its fragment slots for all 16 heads -> cross-head softmax
// is a pure register op. Writes normalized P once.
// 8 warps (2m x 4n), warp tile 32q x 8k. acc: 16 heads x 8 floats = 128 regs.
// ---------------------------------------------------------------------------
__global__ void __launch_bounds__(256,1)
scores_smax(const float* __restrict__ Q, const float* __restrict__ Kmat,
            float* __restrict__ P)
{
    constexpr int LD=DD+4;   // 68
    __shared__ unsigned Qs[64*LD], Ks[32*LD];
    const int tid=threadIdx.x, lane=tid&31, wid=tid>>5;
    const int g=lane>>2, t=lane&3;
    const int wm=wid>>2, wn=wid&3;
    const int b=blockIdx.z, q0=blockIdx.y*64, k0=blockIdx.x*32;
    const float* Qb=Q   +((long)b*SS+q0)*EE;
    const float* Kb=Kmat+((long)b*SS+k0)*EE;

    float4 pq[4], pk[2];
    auto ldg=[&](int h){
#pragma unroll
        for(int i=0;i<4;i++){ int idx=tid+i*256, r=idx>>4, c=(idx&15)<<2;
            pq[i]=*(const float4*)(Qb+(long)r*EE+h*DD+c); }
#pragma unroll
        for(int i=0;i<2;i++){ int idx=tid+i*256, r=idx>>4, c=(idx&15)<<2;
            pk[i]=*(const float4*)(Kb+(long)r*EE+h*DD+c); }
    };
    auto sts=[&](){
#pragma unroll
        for(int i=0;i<4;i++){ int idx=tid+i*256, r=idx>>4, c=(idx&15)<<2;
            Qs[r*LD+c  ]=f2t(pq[i].x); Qs[r*LD+c+1]=f2t(pq[i].y);
            Qs[r*LD+c+2]=f2t(pq[i].z); Qs[r*LD+c+3]=f2t(pq[i].w); }
#pragma unroll
        for(int i=0;i<2;i++){ int idx=tid+i*256, r=idx>>4, c=(idx&15)<<2;
            Ks[r*LD+c  ]=f2t(pk[i].x); Ks[r*LD+c+1]=f2t(pk[i].y);
            Ks[r*LD+c+2]=f2t(pk[i].z); Ks[r*LD+c+3]=f2t(pk[i].w); }
    };

    float acc[HH][2][4];
#pragma unroll
    for(int h=0;h<HH;h++)
#pragma unroll
        for(int mi=0;mi<2;mi++)
#pragma unroll
            for(int f=0;f<4;f++) acc[h][mi][f]=0.f;

    ldg(0); sts(); __syncthreads();
#pragma unroll
    for(int h=0;h<HH;h++){
        if(h+1<HH) ldg(h+1);
#pragma unroll
        for(int kk=0;kk<8;kk++){
            unsigned bf[2];
            const int nb=wn*8+g;
            bf[0]=Ks[nb*LD+kk*8+t  ];
            bf[1]=Ks[nb*LD+kk*8+t+4];
#pragma unroll
            for(int mi=0;mi<2;mi++){
                unsigned af[4];
                const int rb=wm*32+mi*16;
                af[0]=Qs[(rb+g  )*LD+kk*8+t  ];
                af[1]=Qs[(rb+g+8)*LD+kk*8+t  ];
                af[2]=Qs[(rb+g  )*LD+kk*8+t+4];
                af[3]=Qs[(rb+g+8)*LD+kk*8+t+4];
                mma8(acc[h][mi],af,bf);
            }
        }
        if(h+1<HH){ __syncthreads(); sts(); __syncthreads(); }
    }

    // softmax across the 16 heads, per fragment slot (scale 1/8 first)
#pragma unroll
    for(int mi=0;mi<2;mi++)
#pragma unroll
    for(int f=0;f<4;f++){
        float m=-1e30f;
#pragma unroll
        for(int h=0;h<HH;h++){ acc[h][mi][f]*=0.125f; m=fmaxf(m,acc[h][mi][f]); }
        float s=0.f;
#pragma unroll
        for(int h=0;h<HH;h++){ float e=__expf(acc[h][mi][f]-m); acc[h][mi][f]=e; s+=e; }
        const float inv=1.f/s;
#pragma unroll
        for(int h=0;h<HH;h++) acc[h][mi][f]*=inv;
    }

#pragma unroll
    for(int h=0;h<HH;h++){
        float* Ph=P+((long)(b*HH+h))*QK;
#pragma unroll
        for(int mi=0;mi<2;mi++){
            const int r0=q0+wm*32+mi*16+g;
            const int col=k0+wn*8+2*t;
            float2 v0={acc[h][mi][0],acc[h][mi][1]};
            float2 v1={acc[h][mi][2],acc[h][mi][3]};
            *(float2*)(Ph+(long)r0*SS+col)=v0;
            *(float2*)(Ph+(long)(r0+8)*SS+col)=v1;
        }
    }
}

// ---------------------------------------------------------------------------
// P @ V per (b,h): O[2048,64] = P[2048,2048] @ V_bh[2048,64]
// BM=128 BN=64 BK=16, 8 warps (4m x 2n), warp tile 32x32. V transposed to smem.
// ---------------------------------------------------------------------------
__global__ void __launch_bounds__(256,1)
pv_tf32(const float* __restrict__ P, const float* __restrict__ V,
        float* __restrict__ O)
{
    constexpr int BK=16, LD=BK+4;
    __shared__ unsigned As[2][128*LD], Bs[2][64*LD];
    const int tid=threadIdx.x, lane=tid&31, wid=tid>>5;
    const int g=lane>>2, t=lane&3;
    const int wm=wid>>1, wn=wid&1;
    const int z=blockIdx.z, b=z/HH, h=z%HH;
    const int m0=blockIdx.y*128;
    const float* Pb=P+((long)(b*HH+h))*QK;
    const float* Vb=V+(long)b*SS*EE+h*DD;
    float*       Ob=O+(long)b*SS*EE+h*DD;

    float4 pa[2], pv;
    auto ldg=[&](int kt){
#pragma unroll
        for(int j=0;j<2;j++){
            int idx=tid+j*256, r=idx>>2, c=(idx&3)<<2;
            pa[j]=*(const float4*)(Pb+(long)(m0+r)*SS+kt*BK+c);
        }
        { int r=tid>>4, c=(tid&15)<<2;
          pv=*(const float4*)(Vb+(long)(kt*BK+r)*EE+c); }
    };
    auto sts=[&](int buf){
#pragma unroll
        for(int j=0;j<2;j++){
            int idx=tid+j*256, r=idx>>2, c=(idx&3)<<2;
            As[buf][r*LD+c  ]=f2t(pa[j].x); As[buf][r*LD+c+1]=f2t(pa[j].y);
            As[buf][r*LD+c+2]=f2t(pa[j].z); As[buf][r*LD+c+3]=f2t(pa[j].w);
        }
        { int r=tid>>4, c=(tid&15)<<2;          // transpose V -> Bs[d][ks]
          Bs[buf][(c+0)*LD+r]=f2t(pv.x); Bs[buf][(c+1)*LD+r]=f2t(pv.y);
          Bs[buf][(c+2)*LD+r]=f2t(pv.z); Bs[buf][(c+3)*LD+r]=f2t(pv.w); }
    };

    float acc[2][4][4];
#pragma unroll
    for(int i=0;i<2;i++)
#pragma unroll
        for(int j=0;j<4;j++)
#pragma unroll
            for(int k=0;k<4;k++) acc[i][j][k]=0.f;

    const int NT=SS/BK;   // 128
    ldg(0); sts(0); __syncthreads();
    for(int kt=0;kt<NT;kt++){
        const int buf=kt&1;
        if(kt+1<NT) ldg(kt+1);
#pragma unroll
        for(int kk=0;kk<2;kk++){
            unsigned af[2][4], bf[4][2];
#pragma unroll
            for(int mi=0;mi<2;mi++){
                const int rb=wm*32+mi*16;
                af[mi][0]=As[buf][(rb+g  )*LD+kk*8+t  ];
                af[mi][1]=As[buf][(rb+g+8)*LD+kk*8+t  ];
                af[mi][2]=As[buf][(rb+g  )*LD+kk*8+t+4];
                af[mi][3]=As[buf][(rb+g+8)*LD+kk*8+t+4];
            }
#pragma unroll
            for(int nj=0;nj<4;nj++){
                const int d=wn*32+nj*8+g;
                bf[nj][0]=Bs[buf][d*LD+kk*8+t  ];
                bf[nj][1]=Bs[buf][d*LD+kk*8+t+4];
            }
#pragma unroll
            for(int mi=0;mi<2;mi++)
#pragma unroll
                for(int nj=0;nj<4;nj++)
                    mma8(acc[mi][nj],af[mi],bf[nj]);
        }
        if(kt+1<NT) sts((kt+1)&1);
        __syncthreads();
    }
#pragma unroll
    for(int mi=0;mi<2;mi++){
        const int r0=m0+wm*32+mi*16+g;
#pragma unroll
        for(int nj=0;nj<4;nj++){
            const int col=wn*32+nj*8+2*t;
            float2 v0={acc[mi][nj][0],acc[mi][nj][1]};
            float2 v1={acc[mi][nj][2],acc[mi][nj][3]};
            *(float2*)(Ob+(long)r0*EE+col)=v0;
            *(float2*)(Ob+(long)(r0+8)*EE+col)=v1;
        }
    }
}

// ---------------------------------------------------------------------------
extern "C" void kernel_launch(void* const* d_in, const int* in_sizes, int n_in,
                              void* d_out, int out_size)
{
    const float* x  = (const float*)d_in[0];
    const float* Wq = (const float*)d_in[1];
    const float* bq = (const float*)d_in[2];
    const float* Wk = (const float*)d_in[3];
    const float* bk = (const float*)d_in[4];
    const float* Wv = (const float*)d_in[5];
    const float* bv = (const float*)d_in[6];
    const float* Wo = (const float*)d_in[7];
    const float* bo = (const float*)d_in[8];
    float* out = (float*)d_out;

    float *q,*k,*v,*ao,*p;
    cudaGetSymbolAddress((void**)&q,  g_q);
    cudaGetSymbolAddress((void**)&k,  g_k);
    cudaGetSymbolAddress((void**)&v,  g_v);
    cudaGetSymbolAddress((void**)&ao, g_ao);
    cudaGetSymbolAddress((void**)&p,  g_p);

    dim3 blk(256);
    dim3 gproj(EE/128, MROWS/128);       // (8,32)

    proj_tf32<<<gproj,blk>>>(x, Wq, bq, q);
    proj_tf32<<<gproj,blk>>>(x, Wk, bk, k);
    proj_tf32<<<gproj,blk>>>(x, Wv, bv, v);

    dim3 gsc(SS/32, SS/64, BB);          // (64,32,2)
    scores_smax<<<gsc,blk>>>(q, k, p);

    dim3 gpv(1, SS/128, BB*HH);          // (1,16,32)
    pv_tf32<<<gpv,blk>>>(p, v, ao);

    proj_tf32<<<gproj,blk>>>(ao, Wo, bo, out);
}